// round 4
// baseline (speedup 1.0000x reference)
#include <cuda_runtime.h>

#define BB 16
#define SS 4096
#define HH 768
#define NSL 128                 // slices per batch
#define LL 32                   // rows (positions) per slice
#define NEGV (-1e30f)

// ---------------- scratch (static device globals; no allocation) ----------------
__device__ float g_part[BB * NSL * 9];   // per-slice 3x3 semiring partial products
__device__ float g_nump[BB * NSL];       // numerator partial sums (steps t>=1)
__device__ int   g_mskp[BB * NSL];       // mask partial sums (steps t>=1)
__device__ float g_em0[BB * 3];          // emissions row 0 per batch (for alpha0/num)

__device__ __forceinline__ float lse3(float a, float b, float c) {
    float m = fmaxf(a, fmaxf(b, c));
    return m + __logf(__expf(a - m) + __expf(b - m) + __expf(c - m));
}

// ---------------- fused kernel: emissions (smem) + blocked CRF scan --------------
// grid = BB*NSL blocks of 256. Block (b,slice) owns rows [slice*32, slice*32+32).
// 8 warps x 4 rows compute emissions into smem; warp 0 then scans its 32 steps
// (position s = slice*32 + lane; s=0 is not a step -> identity) via shuffle tree.
__global__ void __launch_bounds__(256) fused_kernel(const float* __restrict__ x,
                                                    const float* __restrict__ W,
                                                    const float* __restrict__ bias,
                                                    const int*   __restrict__ y,
                                                    const int*   __restrict__ mask,
                                                    const float* __restrict__ trans) {
    __shared__ float s_em[LL][4];

    int b     = blockIdx.x >> 7;
    int slice = blockIdx.x & (NSL - 1);
    int tid   = threadIdx.x;
    int wid   = tid >> 5;
    int lane  = tid & 31;
    int R     = b * SS + slice * LL;        // global row base for this block

    // ---- emissions phase: warp wid computes rows R + wid*4 .. +3 ----
    {
        int row0 = R + wid * 4;
        const float4* x4 = reinterpret_cast<const float4*>(x);
        const float4* w4 = reinterpret_cast<const float4*>(W);

        float a0[4], a1[4], a2[4];
#pragma unroll
        for (int r = 0; r < 4; r++) { a0[r] = 0.f; a1[r] = 0.f; a2[r] = 0.f; }

#pragma unroll
        for (int j = 0; j < 6; j++) {
            int idx = lane + 32 * j;          // 0..191
            float4 w0 = __ldg(w4 + idx);
            float4 w1 = __ldg(w4 + 192 + idx);
            float4 w2 = __ldg(w4 + 384 + idx);
#pragma unroll
            for (int r = 0; r < 4; r++) {
                float4 xv = __ldg(x4 + (size_t)(row0 + r) * (HH / 4) + idx);
                a0[r] = fmaf(xv.x, w0.x, fmaf(xv.y, w0.y, fmaf(xv.z, w0.z, fmaf(xv.w, w0.w, a0[r]))));
                a1[r] = fmaf(xv.x, w1.x, fmaf(xv.y, w1.y, fmaf(xv.z, w1.z, fmaf(xv.w, w1.w, a1[r]))));
                a2[r] = fmaf(xv.x, w2.x, fmaf(xv.y, w2.y, fmaf(xv.z, w2.z, fmaf(xv.w, w2.w, a2[r]))));
            }
        }
#pragma unroll
        for (int off = 16; off; off >>= 1) {
#pragma unroll
            for (int r = 0; r < 4; r++) {
                a0[r] += __shfl_xor_sync(0xFFFFFFFFu, a0[r], off);
                a1[r] += __shfl_xor_sync(0xFFFFFFFFu, a1[r], off);
                a2[r] += __shfl_xor_sync(0xFFFFFFFFu, a2[r], off);
            }
        }
        float b0 = __ldg(bias + 0), b1 = __ldg(bias + 1), b2 = __ldg(bias + 2);
#pragma unroll
        for (int r = 0; r < 4; r++) {
            if (lane == r) {
                int lr = wid * 4 + r;
                s_em[lr][0] = a0[r] + b0;
                s_em[lr][1] = a1[r] + b1;
                s_em[lr][2] = a2[r] + b2;
            }
        }
    }
    __syncthreads();

    // ---- scan phase: warp 0 only ----
    if (wid == 0) {
        int s_idx = slice * LL + lane;   // position within sequence
        int t     = R + lane;            // flat index

        float tr[9];
#pragma unroll
        for (int i = 0; i < 9; i++) tr[i] = __ldg(trans + i);

        float P[9];
        float nsum = 0.f;
        int   msum = 0;

        int mk = mask[t];
        if (s_idx > 0 && mk) {
            float e0 = s_em[lane][0], e1 = s_em[lane][1], e2 = s_em[lane][2];
#pragma unroll
            for (int i = 0; i < 3; i++) {
                P[i * 3 + 0] = tr[i * 3 + 0] + e0;
                P[i * 3 + 1] = tr[i * 3 + 1] + e1;
                P[i * 3 + 2] = tr[i * 3 + 2] + e2;
            }
            int yt = y[t], yp = y[t - 1];
            nsum = tr[yp * 3 + yt] + s_em[lane][yt];
            msum = 1;
        } else {
#pragma unroll
            for (int i = 0; i < 9; i++) P[i] = NEGV;
            P[0] = 0.f; P[4] = 0.f; P[8] = 0.f;
        }

        if (s_idx == 0 && lane == 0) {           // only (slice 0, lane 0) per batch
            g_em0[b * 3 + 0] = s_em[0][0];
            g_em0[b * 3 + 1] = s_em[0][1];
            g_em0[b * 3 + 2] = s_em[0][2];
        }

        // order-preserving suffix tree: after level st, lane k holds product of
        // chunks [k, k+2*st) -> lane 0 ends with the whole slice product.
#pragma unroll
        for (int st = 1; st < 32; st <<= 1) {
            float Q[9];
#pragma unroll
            for (int i = 0; i < 9; i++) Q[i] = __shfl_down_sync(0xFFFFFFFFu, P[i], st);
            float nq = __shfl_down_sync(0xFFFFFFFFu, nsum, st);
            int   mq = __shfl_down_sync(0xFFFFFFFFu, msum, st);
            float C[9];
#pragma unroll
            for (int i = 0; i < 3; i++) {
#pragma unroll
                for (int j = 0; j < 3; j++) {
                    C[i * 3 + j] = lse3(P[i * 3 + 0] + Q[0 * 3 + j],
                                        P[i * 3 + 1] + Q[1 * 3 + j],
                                        P[i * 3 + 2] + Q[2 * 3 + j]);
                }
            }
#pragma unroll
            for (int i = 0; i < 9; i++) P[i] = C[i];
            nsum += nq;
            msum += mq;
        }

        if (lane == 0) {
            int pi = b * NSL + slice;
#pragma unroll
            for (int i = 0; i < 9; i++) g_part[pi * 9 + i] = P[i];
            g_nump[pi] = nsum;
            g_mskp[pi] = msum;
        }
    }
}

// ---------------- final kernel: chain 128 partials per batch + mean ---------------
// 1 block x 512 threads; warp w owns batch w. Each lane chains 4 consecutive slice
// partials, then a 5-level shuffle tree gives lane 0 the full product.
__global__ void __launch_bounds__(512) crf_final_kernel(const int* __restrict__ y,
                                                        const int* __restrict__ mask,
                                                        const float* __restrict__ start_t,
                                                        const float* __restrict__ end_t,
                                                        float* __restrict__ out) {
    __shared__ float s_llh[BB];

    int w    = threadIdx.x >> 5;     // batch
    int lane = threadIdx.x & 31;

    if (w < BB) {
        int base = w * NSL + lane * 4;

        float P[9];
#pragma unroll
        for (int i = 0; i < 9; i++) P[i] = g_part[base * 9 + i];
        float nsum = g_nump[base];
        int   msum = g_mskp[base];

#pragma unroll
        for (int c = 1; c < 4; c++) {
            const float* Bm = &g_part[(base + c) * 9];
            float C[9];
#pragma unroll
            for (int i = 0; i < 3; i++) {
#pragma unroll
                for (int j = 0; j < 3; j++) {
                    C[i * 3 + j] = lse3(P[i * 3 + 0] + Bm[0 * 3 + j],
                                        P[i * 3 + 1] + Bm[1 * 3 + j],
                                        P[i * 3 + 2] + Bm[2 * 3 + j]);
                }
            }
#pragma unroll
            for (int i = 0; i < 9; i++) P[i] = C[i];
            nsum += g_nump[base + c];
            msum += g_mskp[base + c];
        }

#pragma unroll
        for (int st = 1; st < 32; st <<= 1) {
            float Q[9];
#pragma unroll
            for (int i = 0; i < 9; i++) Q[i] = __shfl_down_sync(0xFFFFFFFFu, P[i], st);
            float nq = __shfl_down_sync(0xFFFFFFFFu, nsum, st);
            int   mq = __shfl_down_sync(0xFFFFFFFFu, msum, st);
            float C[9];
#pragma unroll
            for (int i = 0; i < 3; i++) {
#pragma unroll
                for (int j = 0; j < 3; j++) {
                    C[i * 3 + j] = lse3(P[i * 3 + 0] + Q[0 * 3 + j],
                                        P[i * 3 + 1] + Q[1 * 3 + j],
                                        P[i * 3 + 2] + Q[2 * 3 + j]);
                }
            }
#pragma unroll
            for (int i = 0; i < 9; i++) P[i] = C[i];
            nsum += nq;
            msum += mq;
        }

        if (lane == 0) {
            int b  = w;
            int bS = b * SS;

            float e0 = g_em0[b * 3 + 0], e1 = g_em0[b * 3 + 1], e2 = g_em0[b * 3 + 2];
            float a0 = start_t[0] + e0;
            float a1 = start_t[1] + e1;
            float a2 = start_t[2] + e2;

            float af0 = lse3(a0 + P[0], a1 + P[3], a2 + P[6]);
            float af1 = lse3(a0 + P[1], a1 + P[4], a2 + P[7]);
            float af2 = lse3(a0 + P[2], a1 + P[5], a2 + P[8]);
            float denom = lse3(af0 + end_t[0], af1 + end_t[1], af2 + end_t[2]);

            int y0 = y[bS];
            float em0y = (y0 == 0) ? e0 : ((y0 == 1) ? e1 : e2);
            float num = start_t[y0] + em0y + nsum;
            int slen = mask[bS] + msum;
            int ylast = y[bS + slen - 1];
            num += end_t[ylast];

            s_llh[b] = num - denom;
        }
    }
    __syncthreads();

    if (threadIdx.x < 32) {
        float v = (lane < BB) ? s_llh[lane] : 0.f;
#pragma unroll
        for (int off = 16; off; off >>= 1)
            v += __shfl_xor_sync(0xFFFFFFFFu, v, off);
        if (lane == 0) out[0] = -v / (float)BB;
    }
}

// ---------------- launch ----------------------------------------------------------
extern "C" void kernel_launch(void* const* d_in, const int* in_sizes, int n_in,
                              void* d_out, int out_size) {
    const float* x     = (const float*)d_in[0];
    const int*   y     = (const int*)  d_in[1];
    const int*   mask  = (const int*)  d_in[2];
    const float* W     = (const float*)d_in[3];
    const float* bias  = (const float*)d_in[4];
    const float* st    = (const float*)d_in[5];
    const float* en    = (const float*)d_in[6];
    const float* trans = (const float*)d_in[7];
    float* out = (float*)d_out;

    fused_kernel<<<BB * NSL, 256>>>(x, W, bias, y, mask, trans);
    crf_final_kernel<<<1, 512>>>(y, mask, st, en, out);
}

// round 5
// speedup vs baseline: 1.0370x; 1.0370x over previous
#include <cuda_runtime.h>

#define BB 16
#define SS 4096
#define HH 768
#define NSL 128                 // slices per batch
#define LL 32                   // rows (positions) per slice
#define NEGV (-1e30f)

// ---------------- scratch (static device globals; no allocation) ----------------
__device__ float g_part[BB * NSL * 9];   // per-slice 3x3 semiring partial products
__device__ float g_nump[BB * NSL];       // numerator partial sums (steps t>=1)
__device__ int   g_mskp[BB * NSL];       // mask partial sums (steps t>=1)
__device__ float g_em0[BB * 3];          // emissions row 0 per batch (for alpha0/num)

__device__ __forceinline__ float lse3(float a, float b, float c) {
    float m = fmaxf(a, fmaxf(b, c));
    return m + __logf(__expf(a - m) + __expf(b - m) + __expf(c - m));
}

// ---------------- fused kernel: emissions (smem) + blocked CRF scan --------------
// grid = BB*NSL blocks of 256. Block (b,slice) owns rows [slice*32, slice*32+32).
// 8 warps x 4 rows compute emissions into smem; warp 0 then scans its 32 steps
// (position s = slice*32 + lane; s=0 is not a step -> identity) via shuffle tree.
__global__ void __launch_bounds__(256) fused_kernel(const float* __restrict__ x,
                                                    const float* __restrict__ W,
                                                    const float* __restrict__ bias,
                                                    const int*   __restrict__ y,
                                                    const int*   __restrict__ mask,
                                                    const float* __restrict__ trans,
                                                    float* __restrict__ out) {
    __shared__ float s_em[LL][4];

    int b     = blockIdx.x >> 7;
    int slice = blockIdx.x & (NSL - 1);
    int tid   = threadIdx.x;
    int wid   = tid >> 5;
    int lane  = tid & 31;
    int R     = b * SS + slice * LL;        // global row base for this block

    if (blockIdx.x == 0 && tid == 0) out[0] = 0.f;   // zero accumulator for final kernel

    // ---- emissions phase: warp wid computes rows R + wid*4 .. +3 ----
    {
        int row0 = R + wid * 4;
        const float4* x4 = reinterpret_cast<const float4*>(x);
        const float4* w4 = reinterpret_cast<const float4*>(W);

        float a0[4], a1[4], a2[4];
#pragma unroll
        for (int r = 0; r < 4; r++) { a0[r] = 0.f; a1[r] = 0.f; a2[r] = 0.f; }

#pragma unroll
        for (int j = 0; j < 6; j++) {
            int idx = lane + 32 * j;          // 0..191
            float4 w0 = __ldg(w4 + idx);
            float4 w1 = __ldg(w4 + 192 + idx);
            float4 w2 = __ldg(w4 + 384 + idx);
#pragma unroll
            for (int r = 0; r < 4; r++) {
                float4 xv = __ldg(x4 + (size_t)(row0 + r) * (HH / 4) + idx);
                a0[r] = fmaf(xv.x, w0.x, fmaf(xv.y, w0.y, fmaf(xv.z, w0.z, fmaf(xv.w, w0.w, a0[r]))));
                a1[r] = fmaf(xv.x, w1.x, fmaf(xv.y, w1.y, fmaf(xv.z, w1.z, fmaf(xv.w, w1.w, a1[r]))));
                a2[r] = fmaf(xv.x, w2.x, fmaf(xv.y, w2.y, fmaf(xv.z, w2.z, fmaf(xv.w, w2.w, a2[r]))));
            }
        }
#pragma unroll
        for (int off = 16; off; off >>= 1) {
#pragma unroll
            for (int r = 0; r < 4; r++) {
                a0[r] += __shfl_xor_sync(0xFFFFFFFFu, a0[r], off);
                a1[r] += __shfl_xor_sync(0xFFFFFFFFu, a1[r], off);
                a2[r] += __shfl_xor_sync(0xFFFFFFFFu, a2[r], off);
            }
        }
        float b0 = __ldg(bias + 0), b1 = __ldg(bias + 1), b2 = __ldg(bias + 2);
#pragma unroll
        for (int r = 0; r < 4; r++) {
            if (lane == r) {
                int lr = wid * 4 + r;
                s_em[lr][0] = a0[r] + b0;
                s_em[lr][1] = a1[r] + b1;
                s_em[lr][2] = a2[r] + b2;
            }
        }
    }
    __syncthreads();

    // ---- scan phase: warp 0 only ----
    if (wid == 0) {
        int s_idx = slice * LL + lane;   // position within sequence
        int t     = R + lane;            // flat index

        float tr[9];
#pragma unroll
        for (int i = 0; i < 9; i++) tr[i] = __ldg(trans + i);

        float P[9];
        float nsum = 0.f;
        int   msum = 0;

        int mk = mask[t];
        if (s_idx > 0 && mk) {
            float e0 = s_em[lane][0], e1 = s_em[lane][1], e2 = s_em[lane][2];
#pragma unroll
            for (int i = 0; i < 3; i++) {
                P[i * 3 + 0] = tr[i * 3 + 0] + e0;
                P[i * 3 + 1] = tr[i * 3 + 1] + e1;
                P[i * 3 + 2] = tr[i * 3 + 2] + e2;
            }
            int yt = y[t], yp = y[t - 1];
            nsum = tr[yp * 3 + yt] + s_em[lane][yt];
            msum = 1;
        } else {
#pragma unroll
            for (int i = 0; i < 9; i++) P[i] = NEGV;
            P[0] = 0.f; P[4] = 0.f; P[8] = 0.f;
        }

        if (s_idx == 0 && lane == 0) {           // only (slice 0, lane 0) per batch
            g_em0[b * 3 + 0] = s_em[0][0];
            g_em0[b * 3 + 1] = s_em[0][1];
            g_em0[b * 3 + 2] = s_em[0][2];
        }

        // order-preserving suffix tree: lane 0 ends with the whole slice product.
#pragma unroll
        for (int st = 1; st < 32; st <<= 1) {
            float Q[9];
#pragma unroll
            for (int i = 0; i < 9; i++) Q[i] = __shfl_down_sync(0xFFFFFFFFu, P[i], st);
            float nq = __shfl_down_sync(0xFFFFFFFFu, nsum, st);
            int   mq = __shfl_down_sync(0xFFFFFFFFu, msum, st);
            float C[9];
#pragma unroll
            for (int i = 0; i < 3; i++) {
#pragma unroll
                for (int j = 0; j < 3; j++) {
                    C[i * 3 + j] = lse3(P[i * 3 + 0] + Q[0 * 3 + j],
                                        P[i * 3 + 1] + Q[1 * 3 + j],
                                        P[i * 3 + 2] + Q[2 * 3 + j]);
                }
            }
#pragma unroll
            for (int i = 0; i < 9; i++) P[i] = C[i];
            nsum += nq;
            msum += mq;
        }

        if (lane == 0) {
            int pi = b * NSL + slice;
#pragma unroll
            for (int i = 0; i < 9; i++) g_part[pi * 9 + i] = P[i];
            g_nump[pi] = nsum;
            g_mskp[pi] = msum;
        }
    }
}

// ---------------- final kernel: entry-parallel tree over 128 partials ------------
// grid = BB blocks (one per batch) x 512 threads. Each tree level combines pairs
// of 3x3 matrices with ONE lse3 per thread (9 entries of a pair done by 9 threads),
// compute-then-writeback to avoid in-place races. Serial depth = 7 lse3 levels.
__global__ void __launch_bounds__(512) crf_final_kernel(const int* __restrict__ y,
                                                        const int* __restrict__ mask,
                                                        const float* __restrict__ start_t,
                                                        const float* __restrict__ end_t,
                                                        float* __restrict__ out) {
    __shared__ float sM[NSL * 9];
    __shared__ float sN[NSL];
    __shared__ int   sK[NSL];

    int b   = blockIdx.x;
    int tid = threadIdx.x;

    for (int i = tid; i < NSL * 9; i += 512) sM[i] = g_part[b * NSL * 9 + i];
    if (tid < NSL) { sN[tid] = g_nump[b * NSL + tid]; sK[tid] = g_mskp[b * NSL + tid]; }
    __syncthreads();

    for (int st = 1; st < NSL; st <<= 1) {
        int pairs = NSL / (2 * st);
        int jobs  = pairs * 9;

        float Cv[2]; int off[2]; int cnt = 0;
        for (int j = tid; j < jobs; j += 512) {
            int p = j / 9, e = j - p * 9;
            int i = e / 3, c = e - i * 3;
            int m = p * (2 * st);
            const float* A  = &sM[m * 9];
            const float* Bm = &sM[(m + st) * 9];
            Cv[cnt]  = lse3(A[i * 3 + 0] + Bm[0 + c],
                            A[i * 3 + 1] + Bm[3 + c],
                            A[i * 3 + 2] + Bm[6 + c]);
            off[cnt] = m * 9 + e;
            cnt++;
        }
        float nv = 0.f; int kv = 0; bool dosum = (tid < pairs);
        if (dosum) { int m = tid * 2 * st; nv = sN[m] + sN[m + st]; kv = sK[m] + sK[m + st]; }
        __syncthreads();
        for (int q = 0; q < cnt; q++) sM[off[q]] = Cv[q];
        if (dosum) { int m = tid * 2 * st; sN[m] = nv; sK[m] = kv; }
        __syncthreads();
    }

    if (tid == 0) {
        int bS = b * SS;
        float e0 = g_em0[b * 3 + 0], e1 = g_em0[b * 3 + 1], e2 = g_em0[b * 3 + 2];
        float a0 = start_t[0] + e0;
        float a1 = start_t[1] + e1;
        float a2 = start_t[2] + e2;

        float af0 = lse3(a0 + sM[0], a1 + sM[3], a2 + sM[6]);
        float af1 = lse3(a0 + sM[1], a1 + sM[4], a2 + sM[7]);
        float af2 = lse3(a0 + sM[2], a1 + sM[5], a2 + sM[8]);
        float denom = lse3(af0 + end_t[0], af1 + end_t[1], af2 + end_t[2]);

        int y0 = y[bS];
        float em0y = (y0 == 0) ? e0 : ((y0 == 1) ? e1 : e2);
        float num  = start_t[y0] + em0y + sN[0];
        int   slen = mask[bS] + sK[0];
        num += end_t[y[bS + slen - 1]];

        atomicAdd(out, -(num - denom) / (float)BB);
    }
}

// ---------------- launch ----------------------------------------------------------
extern "C" void kernel_launch(void* const* d_in, const int* in_sizes, int n_in,
                              void* d_out, int out_size) {
    const float* x     = (const float*)d_in[0];
    const int*   y     = (const int*)  d_in[1];
    const int*   mask  = (const int*)  d_in[2];
    const float* W     = (const float*)d_in[3];
    const float* bias  = (const float*)d_in[4];
    const float* st    = (const float*)d_in[5];
    const float* en    = (const float*)d_in[6];
    const float* trans = (const float*)d_in[7];
    float* out = (float*)d_out;

    fused_kernel<<<BB * NSL, 256>>>(x, W, bias, y, mask, trans, out);
    crf_final_kernel<<<BB, 512>>>(y, mask, st, en, out);
}